// round 14
// baseline (speedup 1.0000x reference)
#include <cuda_runtime.h>
#include <cuda_fp16.h>

// N=524288 residues, 21 residue types, 8 rigid frames, 24 atoms (12 atom-pairs).
// 3 threads per residue (one per frame row-group) -> fg[8][4] = 32 regs/thread.
static constexpr int BT  = 192;          // threads per block = RPB * 3
static constexpr int RPB = 64;           // residues per block
static constexpr int W   = 65;           // uint2 row stride for frames (65 = 1 mod 32)

// Shared memory layout (word offsets)
static constexpr int S_TRG    = 0;                    // trans re-staged: [r][rg][2 float2][rt] = 2016 floats
static constexpr int S_RIGP   = S_TRG    + 96*21;     // 12*3*21 float2 = 1512 words
static constexpr int S_RT     = S_RIGP   + 12*3*21*2; // RPB ints
static constexpr int S_TDEPP  = S_RT     + RPB;       // 2*21 u32 packed tdep bytes
static constexpr int S_RDPAIR = S_TDEPP  + 2*21;      // 12*21 u16 = 126 words
static constexpr int S_OPR2   = S_RDPAIR + 126;       // 24 rows * W uint2
static constexpr int SMEM_WORDS = S_OPR2 + 24 * W * 2;
static constexpr int SMEM_BYTES = SMEM_WORDS * 4;     // 27,520 B -> 4 blocks/SM (if regs <= 80)

static_assert(S_OPR2 % 2 == 0, "uint2 region must be 8B aligned");

__global__ void __launch_bounds__(BT, 4)
backbone_kernel(const int* __restrict__ rtype,
                const float* __restrict__ bb,       // (N,4,3)
                const float* __restrict__ pos0,     // (N,3)
                const float* __restrict__ sc,       // (N,7,2)
                const float* __restrict__ g_trans,  // (21,8,4,3)
                const float* __restrict__ g_rig,    // (21,24,3)
                const int* __restrict__ g_tdep,     // (21,8)
                const int* __restrict__ g_rdep,     // (21,24)
                float* __restrict__ out, int nres)
{
    extern __shared__ float sm[];
    float2*         s_trg2   = (float2*)(sm + S_TRG);
    float2*         s_rigp   = (float2*)(sm + S_RIGP);
    int*            s_rt     = (int*)(sm + S_RT);
    unsigned*       s_tdepp  = (unsigned*)(sm + S_TDEPP);
    unsigned short* s_rdpair = (unsigned short*)(sm + S_RDPAIR);
    uint2*          s_opr2   = (uint2*)(sm + S_OPR2);  // idx: (frame*3 + rg)*W + resL

    const int tid = threadIdx.x;

    // ---- stage tables ----
    {
        // trans: target float = (((r*3+rg)*2 + (j>>1))*21 + rt)*2 + (j&1)
        // where row<3 -> (rg=row, j=col), row==3 -> (rg=col, j=3).
        float* trgf = (float*)s_trg2;
        for (int i = tid; i < 96 * 21; i += BT) {
            const int rtt = i / 96, comp = i % 96;
            const int r = comp / 12, rc = comp % 12;
            const int row = rc / 3, col = rc % 3;
            const int rg = (row < 3) ? row : col;
            const int j  = (row < 3) ? col : 3;
            trgf[(((r*3 + rg)*2 + (j >> 1))*21 + rtt)*2 + (j & 1)] = g_trans[i];
        }
        // rig packed per atom-pair (R13 layout)
        float* rpf = (float*)s_rigp;
        for (int i = tid; i < 72 * 21; i += BT) {
            const int rtt = i / 72, comp = i % 72;
            const int a = comp / 3, j = comp % 3;
            const int p = a >> 1, flat = (a & 1) * 3 + j;
            rpf[((p * 3 + (flat >> 1)) * 21 + rtt) * 2 + (flat & 1)] = g_rig[i];
        }
        for (int i = tid; i < 12 * 21; i += BT) {
            const int p = i % 12, rtt = i / 12;
            const unsigned r0 = (unsigned)g_rdep[rtt * 24 + 2*p]     & 0xFFu;
            const unsigned r1 = (unsigned)g_rdep[rtt * 24 + 2*p + 1] & 0xFFu;
            s_rdpair[p * 21 + rtt] = (unsigned short)(r0 | (r1 << 8));
        }
        for (int i = tid; i < 2 * 21; i += BT) {
            const int rtt = i >> 1, h = i & 1;
            unsigned wv = 0;
            #pragma unroll
            for (int b = 0; b < 4; b++)
                wv |= ((unsigned)g_tdep[rtt * 8 + h * 4 + b] & 0xFFu) << (8 * b);
            s_tdepp[i] = wv;
        }
    }
    __syncthreads();

    // ---- thread mapping: (residue, row-group) ----
    const int resL = tid / 3;            // 0..63
    const int rg   = tid - resL * 3;     // 0..2
    const long resG = (long)blockIdx.x * RPB + resL;
    const int nc = (resG < (long)nres) ? (int)resG : (nres - 1);
    const int rt = rtype[nc];
    s_rt[resL] = rt;                     // 3 writers, same value

    const unsigned dlo = s_tdepp[rt * 2 + 0];
    const unsigned dhi = s_tdepp[rt * 2 + 1];

    // ---- per-residue inputs (adjacent lanes share lines -> merged wavefronts) ----
    const float4* bb4 = (const float4*)bb + (size_t)nc * 3;
    float4 b0 = bb4[0], b1 = bb4[1], b2 = bb4[2];
    const float2* sc2 = (const float2*)sc + (size_t)nc * 7;
    float2 cs[7];
    #pragma unroll
    for (int r = 0; r < 7; r++) cs[r] = sc2[r];

    const float Y00=b0.x, Y01=b0.y, Y02=b0.z;
    const float Y10=b0.w, Y11=b1.x, Y12=b1.y;
    const float Y20=b1.z, Y21=b1.w, Y22=b2.x;
    const float l0 = b2.y + pos0[nc*3+0];
    const float l1 = b2.z + pos0[nc*3+1];
    const float l2 = b2.w + pos0[nc*3+2];

    // ---- register-resident row-group chain: fg[r] = {C_i0, C_i1, C_i2, Ct_i} ----
    float fg[8][4];

    #define STORE_RG(R) do {                                                      \
        __half2 h0 = __floats2half2_rn(fg[R][0], fg[R][1]);                       \
        __half2 h1 = __floats2half2_rn(fg[R][2], fg[R][3]);                       \
        uint2 u; u.x = *(unsigned*)&h0; u.y = *(unsigned*)&h1;                    \
        s_opr2[((R)*3 + rg)*W + resL] = u;                                        \
    } while (0)

    // frame 0: row-group rg of combine(T[rt][0], opr0) — needs only own X row-group
    {
        const float2 a = s_trg2[(rg*2 + 0)*21 + rt];   // (X_3rg, X_3rg+1)
        const float2 b = s_trg2[(rg*2 + 1)*21 + rt];   // (X_3rg+2, Xt_rg)
        fg[0][0] = a.x*Y00 + a.y*Y10 + b.x*Y20;
        fg[0][1] = a.x*Y01 + a.y*Y11 + b.x*Y21;
        fg[0][2] = a.x*Y02 + a.y*Y12 + b.x*Y22;
        fg[0][3] = a.x*l0  + a.y*l1  + b.x*l2 + b.y;
        STORE_RG(0);
    }

    // frames 1..7: full A rebuilt per lane; P = own row-group of fg[dep] via SELs
    #pragma unroll
    for (int r = 1; r < 8; r++) {
        const float cc = cs[r-1].x, ss = cs[r-1].y;

        float X[12];
        #pragma unroll
        for (int rgp = 0; rgp < 3; rgp++) {
            const float2 a = s_trg2[((r*3 + rgp)*2 + 0)*21 + rt];
            const float2 b = s_trg2[((r*3 + rgp)*2 + 1)*21 + rt];
            X[3*rgp]   = a.x; X[3*rgp+1] = a.y;
            X[3*rgp+2] = b.x; X[9+rgp]   = b.y;
        }

        // A = T[rt][r] composed with rot_x(c,s)   (translation unchanged)
        const float A0 = X[0], A1 = X[1]*cc + X[2]*ss, A2 = X[2]*cc - X[1]*ss;
        const float A3 = X[3], A4 = X[4]*cc + X[5]*ss, A5 = X[5]*cc - X[4]*ss;
        const float A6 = X[6], A7 = X[7]*cc + X[8]*ss, A8 = X[8]*cc - X[7]*ss;
        const float At0 = X[9], At1 = X[10], At2 = X[11];

        const int dep = (int)(((r < 4 ? dlo : dhi) >> ((r & 3) * 8)) & 0xFFu);

        float P0 = fg[0][0], P1 = fg[0][1], P2 = fg[0][2], P3 = fg[0][3];
        #pragma unroll
        for (int j = 1; j < 8; j++) {
            if (j < r) {                 // compile-time prune: dep < r
                const bool m = (dep == j);
                P0 = m ? fg[j][0] : P0;
                P1 = m ? fg[j][1] : P1;
                P2 = m ? fg[j][2] : P2;
                P3 = m ? fg[j][3] : P3;
            }
        }

        fg[r][0] = P0*A0  + P1*A3  + P2*A6;
        fg[r][1] = P0*A1  + P1*A4  + P2*A7;
        fg[r][2] = P0*A2  + P1*A5  + P2*A8;
        fg[r][3] = P0*At0 + P1*At1 + P2*At2 + P3;
        STORE_RG(r);
    }

    __syncthreads();   // atom phase reads frames produced by other warps

    // ---- block-cooperative pair-task atom phase ----
    // task q = it*BT + tid over (res = q/12, pair p = q%12); atoms (2p, 2p+1).
    // Output addr = blockBase*72 + 6q -> thread-contiguous.
    {
        float* outb = out + (long)blockIdx.x * RPB * 72;
        const long blockRes0 = (long)blockIdx.x * RPB;

        #pragma unroll
        for (int it = 0; it < 4; ++it) {
            const int q   = it * BT + tid;         // < 768
            const int res = q / 12;
            const int p   = q - res * 12;
            const int rtl = s_rt[res];
            const unsigned short rp = s_rdpair[p * 21 + rtl];
            const int rd0 = rp & 0xFF;
            const int rd1 = rp >> 8;

            // frame slots: uint2 halves = (M_i0, M_i1 | M_i2, t_i) per row-group i
            uint2 a0 = s_opr2[(rd0*3 + 0)*W + res];
            uint2 a1 = s_opr2[(rd0*3 + 1)*W + res];
            uint2 a2 = s_opr2[(rd0*3 + 2)*W + res];
            uint2 c0 = s_opr2[(rd1*3 + 0)*W + res];
            uint2 c1 = s_opr2[(rd1*3 + 1)*W + res];
            uint2 c2 = s_opr2[(rd1*3 + 2)*W + res];

            const float2 g0 = s_rigp[(p*3 + 0) * 21 + rtl];  // (v0a, v1a)
            const float2 g1 = s_rigp[(p*3 + 1) * 21 + rtl];  // (v2a, v0b)
            const float2 g2 = s_rigp[(p*3 + 2) * 21 + rtl];  // (v1b, v2b)

            #define RG_DOT(U, V0, V1, V2)                                          \
                (__half22float2(*(const __half2*)&(U).x).x * (V0) +                \
                 __half22float2(*(const __half2*)&(U).x).y * (V1) +                \
                 __half22float2(*(const __half2*)&(U).y).x * (V2) +                \
                 __half22float2(*(const __half2*)&(U).y).y)

            const float o0 = RG_DOT(a0, g0.x, g0.y, g1.x);
            const float o1 = RG_DOT(a1, g0.x, g0.y, g1.x);
            const float o2 = RG_DOT(a2, g0.x, g0.y, g1.x);
            const float o3 = RG_DOT(c0, g1.y, g2.x, g2.y);
            const float o4 = RG_DOT(c1, g1.y, g2.x, g2.y);
            const float o5 = RG_DOT(c2, g1.y, g2.x, g2.y);

            if (blockRes0 + res < (long)nres) {
                float* pp = outb + q * 6;
                *(float2*)(pp + 0) = make_float2(o0, o1);
                *(float2*)(pp + 2) = make_float2(o2, o3);
                *(float2*)(pp + 4) = make_float2(o4, o5);
            }
        }
    }

    // ---- second output: opr[:,0] (frame 0, fp16 halves), block-cooperative ----
    {
        float* o2base = out + (long)nres * 72 + (long)blockIdx.x * RPB * 12;
        const long blockRes0 = (long)blockIdx.x * RPB;

        #pragma unroll
        for (int it = 0; it < 4; ++it) {
            const int k   = it * BT + tid;         // < 768
            const int res = k / 12;
            const int c   = k - res * 12;
            // comp c -> (rowgroup, half): c<9: (c/3, c%3); else (c-9, 3)
            const int rgc = (c < 9) ? (c / 3) : (c - 9);
            const int h   = (c < 9) ? (c % 3) : 3;
            const char* basep = (const char*)&s_opr2[(0*3 + rgc)*W + res];
            const __half hv = *(const __half*)(basep + h * 2);
            if (blockRes0 + res < (long)nres) o2base[k] = __half2float(hv);
        }
    }
}

extern "C" void kernel_launch(void* const* d_in, const int* in_sizes, int n_in,
                              void* d_out, int out_size)
{
    const int*   rtype   = (const int*)  d_in[0];
    const float* bb      = (const float*)d_in[1];
    const float* pos0    = (const float*)d_in[2];
    const float* sc      = (const float*)d_in[3];
    const float* g_trans = (const float*)d_in[4];
    const float* g_rig   = (const float*)d_in[5];
    const int*   g_tdep  = (const int*)  d_in[6];
    const int*   g_rdep  = (const int*)  d_in[7];
    float* out = (float*)d_out;

    const int nres = in_sizes[0];

    cudaFuncSetAttribute(backbone_kernel,
                         cudaFuncAttributeMaxDynamicSharedMemorySize, SMEM_BYTES);

    const int grid = (nres + RPB - 1) / RPB;
    backbone_kernel<<<grid, BT, SMEM_BYTES>>>(rtype, bb, pos0, sc,
                                              g_trans, g_rig, g_tdep, g_rdep,
                                              out, nres);
}

// round 15
// speedup vs baseline: 1.3106x; 1.3106x over previous
#include <cuda_runtime.h>
#include <cuda_fp16.h>

// N=524288 residues, 21 residue types, 8 rigid frames, 24 atoms (12 atom-pairs).
static constexpr int BT = 256;   // threads per block, 1 thread = 1 residue in build phase
static constexpr int W  = 257;   // uint2-row stride for frames (257 == 1 mod 32 -> conflict-free)

// Shared memory layout (word offsets)
static constexpr int S_TRANS2 = 0;                     // 48*21 float2 = 2016 words
static constexpr int S_RIGA   = S_TRANS2 + 48*21*2;    // 12*21 uint2 (half2 v0a,v1a | v2a,v0b) = 504
static constexpr int S_RIGB   = S_RIGA   + 12*21*2;    // 12*21 u32  (half2 v1b,v2b) = 252
static constexpr int S_RT     = S_RIGB   + 12*21;      // BT ints
static constexpr int S_TDEPP  = S_RT     + BT;         // 2*21 u32 packed tdep bytes
static constexpr int S_RDPAIR = S_TDEPP  + 2*21;       // 12*21 u16 = 126 words
static constexpr int S_SBB    = S_RDPAIR + 126;        // staged bb: BT*12 floats = 3072 (16B-aligned)
static constexpr int S_SP0    = S_SBB    + BT*12;      // staged pos0: BT*3 = 768
static constexpr int S_SSC    = S_SP0    + BT*3;       // staged sc: BT rows * 15 words = 3840
static constexpr int S_OPR2   = S_SSC    + BT*15;      // 24 rows * W uint2 = 12336 words
static constexpr int SMEM_WORDS = S_OPR2 + 24 * W * 2;
static constexpr int SMEM_BYTES = SMEM_WORDS * 4;      // 92,848 B -> 2 blocks/SM

static_assert(S_SBB  % 4 == 0, "bb staging must be 16B aligned");
static_assert(S_SP0  % 4 == 0, "pos0 staging must be 16B aligned");
static_assert(S_OPR2 % 2 == 0, "uint2 region must be 8B aligned");

__global__ void __launch_bounds__(BT, 2)
backbone_kernel(const int* __restrict__ rtype,
                const float* __restrict__ bb,       // (N,4,3)
                const float* __restrict__ pos0,     // (N,3)
                const float* __restrict__ sc,       // (N,7,2)
                const float* __restrict__ g_trans,  // (21,8,4,3)
                const float* __restrict__ g_rig,    // (21,24,3)
                const int* __restrict__ g_tdep,     // (21,8)
                const int* __restrict__ g_rdep,     // (21,24)
                float* __restrict__ out, int nres)
{
    extern __shared__ float sm[];
    float2*         s_trans2 = (float2*)(sm + S_TRANS2);
    uint2*          s_riga   = (uint2*)(sm + S_RIGA);
    unsigned*       s_rigb   = (unsigned*)(sm + S_RIGB);
    int*            s_rt     = (int*)(sm + S_RT);
    unsigned*       s_tdepp  = (unsigned*)(sm + S_TDEPP);
    unsigned short* s_rdpair = (unsigned short*)(sm + S_RDPAIR);
    uint2*          s_opr2   = (uint2*)(sm + S_OPR2);  // index: (frame*3 + q)*W + tid

    const int tid  = threadIdx.x;
    const int lane = tid & 31;
    const int warp = tid >> 5;

    // ================= staging phase =================
    {
        // trans transposed [pair][rt] (stride 21 -> conflict-free divergent reads)
        float* t2f = (float*)s_trans2;
        for (int i = tid; i < 96 * 21; i += BT) {
            const int rtt = i / 96, comp = i % 96;
            t2f[((comp >> 1) * 21 + rtt) * 2 + (comp & 1)] = g_trans[i];
        }
        // rig packed per atom-pair as half2 triplets
        for (int i = tid; i < 12 * 21; i += BT) {
            const int p = i % 12, rtt = i / 12;
            const float* gr = g_rig + rtt * 72 + p * 6;   // atoms 2p, 2p+1
            __half2 ha = __floats2half2_rn(gr[0], gr[1]); // (v0a, v1a)
            __half2 hb = __floats2half2_rn(gr[2], gr[3]); // (v2a, v0b)
            __half2 hc = __floats2half2_rn(gr[4], gr[5]); // (v1b, v2b)
            uint2 u; u.x = *(unsigned*)&ha; u.y = *(unsigned*)&hb;
            s_riga[p * 21 + rtt] = u;
            s_rigb[p * 21 + rtt] = *(unsigned*)&hc;
        }
        for (int i = tid; i < 12 * 21; i += BT) {
            const int p = i % 12, rtt = i / 12;
            const unsigned r0 = (unsigned)g_rdep[rtt * 24 + 2*p]     & 0xFFu;
            const unsigned r1 = (unsigned)g_rdep[rtt * 24 + 2*p + 1] & 0xFFu;
            s_rdpair[p * 21 + rtt] = (unsigned short)(r0 | (r1 << 8));
        }
        for (int i = tid; i < 2 * 21; i += BT) {
            const int rtt = i >> 1, h = i & 1;
            unsigned wv = 0;
            #pragma unroll
            for (int b = 0; b < 4; b++)
                wv |= ((unsigned)g_tdep[rtt * 8 + h * 4 + b] & 0xFFu) << (8 * b);
            s_tdepp[i] = wv;
        }

        // ---- coalesced input staging for this block's BT residues ----
        // bb: straight float4 copy (12 floats/res, float4 never straddles a residue)
        {
            const float4* bbg4 = (const float4*)bb;
            const long base = (long)blockIdx.x * BT * 3;
            float4* dst = (float4*)(sm + S_SBB);
            #pragma unroll
            for (int e = tid; e < BT * 3; e += BT) {
                const long g = base + e;
                if (g < (long)nres * 3) dst[e] = bbg4[g];
            }
        }
        // pos0: straight float4 copy (BT*3/4 = 192 vec4)
        {
            const float4* p0g4 = (const float4*)pos0;
            const long base = (long)blockIdx.x * (BT * 3 / 4);
            float4* dst = (float4*)(sm + S_SP0);
            for (int e = tid; e < BT * 3 / 4; e += BT) {
                const long g = base + e;
                if (g < ((long)nres * 3) >> 2) dst[e] = p0g4[g];
            }
        }
        // sc: coalesced scalar copy with reshape to stride-15 rows (gcd(15,32)=1)
        {
            const long base = (long)blockIdx.x * BT * 14;
            #pragma unroll
            for (int e = tid; e < BT * 14; e += BT) {
                const long g = base + e;
                if (g < (long)nres * 14) {
                    const int res = e / 14, c = e - res * 14;
                    sm[S_SSC + res * 15 + c] = sc[g];
                }
            }
        }
    }
    __syncthreads();

    const long resG = (long)blockIdx.x * BT + tid;
    const int nc = (resG < (long)nres) ? (int)resG : (nres - 1);
    const int rt = rtype[nc];            // coalesced (4B stride)
    s_rt[tid] = rt;

    const unsigned dlo = s_tdepp[rt * 2 + 0];
    const unsigned dhi = s_tdepp[rt * 2 + 1];

    // ---- per-residue inputs from smem staging (conflict-free) ----
    const float4* sb4 = (const float4*)(sm + S_SBB) + tid * 3;   // quad stride 3, gcd(3,8)=1
    float4 b0 = sb4[0], b1 = sb4[1], b2 = sb4[2];
    const float p0x = sm[S_SP0 + tid*3 + 0];
    const float p0y = sm[S_SP0 + tid*3 + 1];
    const float p0z = sm[S_SP0 + tid*3 + 2];
    const float* myc = sm + S_SSC + tid * 15;    // 14 scalars, stride-15 rows

    const float Y00=b0.x, Y01=b0.y, Y02=b0.z;
    const float Y10=b0.w, Y11=b1.x, Y12=b1.y;
    const float Y20=b1.z, Y21=b1.w, Y22=b2.x;
    const float l0 = b2.y + p0x;
    const float l1 = b2.z + p0y;
    const float l2 = b2.w + p0z;

    // ---- register-resident fp32 frames; sequential half2 pairing at store ----
    float f[8][12];

    #define STORE_FRAME(R) do {                                                   \
        __half2 h0 = __floats2half2_rn(f[R][0],  f[R][1]);                        \
        __half2 h1 = __floats2half2_rn(f[R][2],  f[R][3]);                        \
        __half2 h2 = __floats2half2_rn(f[R][4],  f[R][5]);                        \
        __half2 h3 = __floats2half2_rn(f[R][6],  f[R][7]);                        \
        __half2 h4 = __floats2half2_rn(f[R][8],  f[R][9]);                        \
        __half2 h5 = __floats2half2_rn(f[R][10], f[R][11]);                       \
        uint2 u0; u0.x = *(unsigned*)&h0; u0.y = *(unsigned*)&h1;                 \
        uint2 u1; u1.x = *(unsigned*)&h2; u1.y = *(unsigned*)&h3;                 \
        uint2 u2; u2.x = *(unsigned*)&h4; u2.y = *(unsigned*)&h5;                 \
        s_opr2[((R)*3 + 0)*W + tid] = u0;                                         \
        s_opr2[((R)*3 + 1)*W + tid] = u1;                                         \
        s_opr2[((R)*3 + 2)*W + tid] = u2;                                         \
    } while (0)

    // frame 0: combine(T[rt][0], opr0)
    {
        float X[12];
        #pragma unroll
        for (int cp = 0; cp < 6; cp++) {
            float2 x2 = s_trans2[cp * 21 + rt];
            X[2*cp] = x2.x; X[2*cp+1] = x2.y;
        }
        f[0][0] = X[0]*Y00 + X[1]*Y10 + X[2]*Y20;
        f[0][1] = X[0]*Y01 + X[1]*Y11 + X[2]*Y21;
        f[0][2] = X[0]*Y02 + X[1]*Y12 + X[2]*Y22;
        f[0][3] = X[3]*Y00 + X[4]*Y10 + X[5]*Y20;
        f[0][4] = X[3]*Y01 + X[4]*Y11 + X[5]*Y21;
        f[0][5] = X[3]*Y02 + X[4]*Y12 + X[5]*Y22;
        f[0][6] = X[6]*Y00 + X[7]*Y10 + X[8]*Y20;
        f[0][7] = X[6]*Y01 + X[7]*Y11 + X[8]*Y21;
        f[0][8] = X[6]*Y02 + X[7]*Y12 + X[8]*Y22;
        f[0][9]  = X[0]*l0 + X[1]*l1 + X[2]*l2 + X[9];
        f[0][10] = X[3]*l0 + X[4]*l1 + X[5]*l2 + X[10];
        f[0][11] = X[6]*l0 + X[7]*l1 + X[8]*l2 + X[11];
        STORE_FRAME(0);
    }

    // frames 1..7: SEL-selected prev (exact fp32), single fp16 rounding at store
    #pragma unroll
    for (int r = 1; r < 8; r++) {
        const float cc = myc[2*(r-1)];
        const float ss = myc[2*(r-1) + 1];

        float Xr[12];
        #pragma unroll
        for (int cp = 0; cp < 6; cp++) {
            float2 x2 = s_trans2[(r*6 + cp) * 21 + rt];
            Xr[2*cp] = x2.x; Xr[2*cp+1] = x2.y;
        }

        // A = T[rt][r] composed with rot_x(c,s)   (translation unchanged)
        const float A0 = Xr[0], A1 = Xr[1]*cc + Xr[2]*ss, A2 = Xr[2]*cc - Xr[1]*ss;
        const float A3 = Xr[3], A4 = Xr[4]*cc + Xr[5]*ss, A5 = Xr[5]*cc - Xr[4]*ss;
        const float A6 = Xr[6], A7 = Xr[7]*cc + Xr[8]*ss, A8 = Xr[8]*cc - Xr[7]*ss;
        const float At0 = Xr[9], At1 = Xr[10], At2 = Xr[11];

        const int dep = (int)(((r < 4 ? dlo : dhi) >> ((r & 3) * 8)) & 0xFFu);

        float P[12];
        #pragma unroll
        for (int k = 0; k < 12; k++) P[k] = f[0][k];
        #pragma unroll
        for (int j = 1; j < 8; j++) {
            if (j < r) {                 // compile-time prune: dep < r
                const bool m = (dep == j);
                #pragma unroll
                for (int k = 0; k < 12; k++) P[k] = m ? f[j][k] : P[k];
            }
        }

        f[r][0] = P[0]*A0 + P[1]*A3 + P[2]*A6;
        f[r][1] = P[0]*A1 + P[1]*A4 + P[2]*A7;
        f[r][2] = P[0]*A2 + P[1]*A5 + P[2]*A8;
        f[r][3] = P[3]*A0 + P[4]*A3 + P[5]*A6;
        f[r][4] = P[3]*A1 + P[4]*A4 + P[5]*A7;
        f[r][5] = P[3]*A2 + P[4]*A5 + P[5]*A8;
        f[r][6] = P[6]*A0 + P[7]*A3 + P[8]*A6;
        f[r][7] = P[6]*A1 + P[7]*A4 + P[8]*A7;
        f[r][8] = P[6]*A2 + P[7]*A5 + P[8]*A8;
        f[r][9]  = P[0]*At0 + P[1]*At1 + P[2]*At2 + P[9];
        f[r][10] = P[3]*At0 + P[4]*At1 + P[5]*At2 + P[10];
        f[r][11] = P[6]*At0 + P[7]*At1 + P[8]*At2 + P[11];

        STORE_FRAME(r);
    }

    __syncwarp();   // atom phase reads frames of the whole warp (this warp produced them)

    // helper: transform one atom through a half2-packed frame
    #define ATOM_XFORM(U0, U1, U2, V0, V1, V2, O0, O1, O2) do {                   \
        float2 M01   = __half22float2(*(const __half2*)&(U0).x);                  \
        float2 M23   = __half22float2(*(const __half2*)&(U0).y);                  \
        float2 M45   = __half22float2(*(const __half2*)&(U1).x);                  \
        float2 M67   = __half22float2(*(const __half2*)&(U1).y);                  \
        float2 M89   = __half22float2(*(const __half2*)&(U2).x);                  \
        float2 M1011 = __half22float2(*(const __half2*)&(U2).y);                  \
        O0 = M01.x*(V0) + M01.y*(V1) + M23.x*(V2) + M89.y;                        \
        O1 = M23.y*(V0) + M45.x*(V1) + M45.y*(V2) + M1011.x;                      \
        O2 = M67.x*(V0) + M67.y*(V1) + M89.x*(V2) + M1011.y;                      \
    } while (0)

    // ---- warp-cooperative pair-task atom phase ----
    // task q = it*32+lane over (rho = q/12, pairIdx = q%12); atoms (2p, 2p+1).
    // Output addr = warpbase*72 + 6q -> 32 lanes span a contiguous 768B window.
    {
        const int wbase = warp * 32;
        const long resBase = (long)blockIdx.x * BT + wbase;
        float* owarp = out + resBase * 72;

        int rho = (lane < 12) ? 0 : ((lane < 24) ? 1 : 2);
        int p   = lane - rho * 12;

        #pragma unroll
        for (int it = 0; it < 12; ++it) {
            const int trho = wbase + rho;
            const int rtl  = s_rt[trho];
            const unsigned short rp = s_rdpair[p * 21 + rtl];
            const int rd0 = rp & 0xFF;
            const int rd1 = rp >> 8;

            uint2 a0 = s_opr2[(rd0*3 + 0)*W + trho];
            uint2 a1 = s_opr2[(rd0*3 + 1)*W + trho];
            uint2 a2 = s_opr2[(rd0*3 + 2)*W + trho];
            uint2 c0 = s_opr2[(rd1*3 + 0)*W + trho];
            uint2 c1 = s_opr2[(rd1*3 + 1)*W + trho];
            uint2 c2 = s_opr2[(rd1*3 + 2)*W + trho];

            const uint2    ra = s_riga[p * 21 + rtl];
            const unsigned rb = s_rigb[p * 21 + rtl];
            const float2 g0 = __half22float2(*(const __half2*)&ra.x);  // (v0a, v1a)
            const float2 g1 = __half22float2(*(const __half2*)&ra.y);  // (v2a, v0b)
            const float2 g2 = __half22float2(*(const __half2*)&rb);    // (v1b, v2b)

            float o0, o1, o2, o3, o4, o5;
            ATOM_XFORM(a0, a1, a2, g0.x, g0.y, g1.x, o0, o1, o2);
            ATOM_XFORM(c0, c1, c2, g1.y, g2.x, g2.y, o3, o4, o5);

            if (resBase + rho < (long)nres) {
                float* pp = owarp + rho * 72 + p * 6;
                *(float2*)(pp + 0) = make_float2(o0, o1);
                *(float2*)(pp + 2) = make_float2(o2, o3);
                *(float2*)(pp + 4) = make_float2(o4, o5);
            }
            // advance q by 32: p += 8 (mod 12), rho takes the carry (+2, +1 on wrap)
            p += 8; rho += 2;
            if (p >= 12) { p -= 12; rho += 1; }
        }
    }

    // ---- second output: opr[:,0] (frame 0, sequential halves), coalesced ----
    {
        const int wbase = warp * 32;
        const long resBase = (long)blockIdx.x * BT + wbase;
        long rem = (long)nres - resBase;
        const int cnt = (rem >= 32) ? 32 : (rem > 0 ? (int)rem : 0);
        float* o2 = out + (long)nres * 72 + resBase * 12;
        const int tot = cnt * 12;
        for (int k = lane; k < tot; k += 32) {
            const int l = k / 12;
            const int c = k - l * 12;          // component 0..11 -> (q = c/4, half = c%4)
            const char* basep = (const char*)&s_opr2[(c >> 2)*W + wbase + l];
            const __half h = *(const __half*)(basep + (c & 3) * 2);
            o2[k] = __half2float(h);
        }
    }
}

extern "C" void kernel_launch(void* const* d_in, const int* in_sizes, int n_in,
                              void* d_out, int out_size)
{
    const int*   rtype   = (const int*)  d_in[0];
    const float* bb      = (const float*)d_in[1];
    const float* pos0    = (const float*)d_in[2];
    const float* sc      = (const float*)d_in[3];
    const float* g_trans = (const float*)d_in[4];
    const float* g_rig   = (const float*)d_in[5];
    const int*   g_tdep  = (const int*)  d_in[6];
    const int*   g_rdep  = (const int*)  d_in[7];
    float* out = (float*)d_out;

    const int nres = in_sizes[0];

    cudaFuncSetAttribute(backbone_kernel,
                         cudaFuncAttributeMaxDynamicSharedMemorySize, SMEM_BYTES);

    const int grid = (nres + BT - 1) / BT;
    backbone_kernel<<<grid, BT, SMEM_BYTES>>>(rtype, bb, pos0, sc,
                                              g_trans, g_rig, g_tdep, g_rdep,
                                              out, nres);
}

// round 16
// speedup vs baseline: 1.4191x; 1.0828x over previous
#include <cuda_runtime.h>
#include <cuda_fp16.h>

// N=524288 residues, 21 residue types, 8 rigid frames, 24 atoms (6 atom-quads).
static constexpr int BT = 256;   // threads per block, 1 thread = 1 residue in build phase
static constexpr int W  = 257;   // uint2-row stride for frames (257 == 1 mod 32 -> conflict-free)

// Shared memory layout (word offsets)
static constexpr int S_TRANS2 = 0;                    // 48*21 float2 = 2016 words
static constexpr int S_RIGQ   = S_TRANS2 + 48*21*2;   // 6*3*21 uint2 (12 halves per quad) = 756 words
static constexpr int S_RT     = S_RIGQ   + 6*3*21*2;  // BT ints
static constexpr int S_TDEPP  = S_RT     + BT;        // 2*21 u32 packed tdep bytes
static constexpr int S_RDQUAD = S_TDEPP  + 2*21;      // 6*21 u32 (4 rdep bytes per quad) = 126 words
static constexpr int S_OPR2   = S_RDQUAD + 126;       // 24 rows * W uint2 = 12336 words
static constexpr int SMEM_WORDS = S_OPR2 + 24 * W * 2;
static constexpr int SMEM_BYTES = SMEM_WORDS * 4;     // 62,128 B -> 2 blocks/SM

static_assert(S_OPR2 % 2 == 0, "uint2 region must be 8B aligned");
static_assert(S_RIGQ % 2 == 0, "rigq region must be 8B aligned");

__global__ void __launch_bounds__(BT, 2)
backbone_kernel(const int* __restrict__ rtype,
                const float* __restrict__ bb,       // (N,4,3)
                const float* __restrict__ pos0,     // (N,3)
                const float* __restrict__ sc,       // (N,7,2)
                const float* __restrict__ g_trans,  // (21,8,4,3)
                const float* __restrict__ g_rig,    // (21,24,3)
                const int* __restrict__ g_tdep,     // (21,8)
                const int* __restrict__ g_rdep,     // (21,24)
                float* __restrict__ out, int nres)
{
    extern __shared__ float sm[];
    float2*         s_trans2 = (float2*)(sm + S_TRANS2);
    uint2*          s_rigq   = (uint2*)(sm + S_RIGQ);
    int*            s_rt     = (int*)(sm + S_RT);
    unsigned*       s_tdepp  = (unsigned*)(sm + S_TDEPP);
    unsigned*       s_rdquad = (unsigned*)(sm + S_RDQUAD);
    uint2*          s_opr2   = (uint2*)(sm + S_OPR2);  // index: (frame*3 + q)*W + tid

    const int tid  = threadIdx.x;
    const int lane = tid & 31;
    const int warp = tid >> 5;

    // ---- stage tables (stride-21 transposed -> conflict-free divergent-rt reads) ----
    {
        float* t2f = (float*)s_trans2;
        for (int i = tid; i < 96 * 21; i += BT) {
            const int rtt = i / 96, comp = i % 96;
            t2f[((comp >> 1) * 21 + rtt) * 2 + (comp & 1)] = g_trans[i];
        }
        // rig packed per atom-quad as 6 half2 (12 values: atoms 4q..4q+3)
        for (int i = tid; i < 6 * 21; i += BT) {
            const int q = i % 6, rtt = i / 6;
            const float* gr = g_rig + rtt * 72 + q * 12;
            #pragma unroll
            for (int k = 0; k < 3; k++) {
                __half2 hx = __floats2half2_rn(gr[4*k + 0], gr[4*k + 1]);
                __half2 hy = __floats2half2_rn(gr[4*k + 2], gr[4*k + 3]);
                uint2 u; u.x = *(unsigned*)&hx; u.y = *(unsigned*)&hy;
                s_rigq[(q * 3 + k) * 21 + rtt] = u;
            }
        }
        // rdep packed 4 bytes per quad
        for (int i = tid; i < 6 * 21; i += BT) {
            const int q = i % 6, rtt = i / 6;
            unsigned wv = 0;
            #pragma unroll
            for (int b = 0; b < 4; b++)
                wv |= ((unsigned)g_rdep[rtt * 24 + q * 4 + b] & 0xFFu) << (8 * b);
            s_rdquad[q * 21 + rtt] = wv;
        }
        for (int i = tid; i < 2 * 21; i += BT) {
            const int rtt = i >> 1, h = i & 1;
            unsigned wv = 0;
            #pragma unroll
            for (int b = 0; b < 4; b++)
                wv |= ((unsigned)g_tdep[rtt * 8 + h * 4 + b] & 0xFFu) << (8 * b);
            s_tdepp[i] = wv;
        }
    }
    __syncthreads();

    const long resG = (long)blockIdx.x * BT + tid;
    const int nc = (resG < (long)nres) ? (int)resG : (nres - 1);
    const int rt = rtype[nc];
    s_rt[tid] = rt;

    const unsigned dlo = s_tdepp[rt * 2 + 0];
    const unsigned dhi = s_tdepp[rt * 2 + 1];

    // ---- per-residue inputs: ALL prefetched to registers before the chain (R8/R13 lesson) ----
    const float4* bb4 = (const float4*)bb + (size_t)nc * 3;
    float4 b0 = bb4[0], b1 = bb4[1], b2 = bb4[2];
    const float2* sc2 = (const float2*)sc + (size_t)nc * 7;
    float2 cs[7];
    #pragma unroll
    for (int r = 0; r < 7; r++) cs[r] = sc2[r];

    const float Y00=b0.x, Y01=b0.y, Y02=b0.z;
    const float Y10=b0.w, Y11=b1.x, Y12=b1.y;
    const float Y20=b1.z, Y21=b1.w, Y22=b2.x;
    const float l0 = b2.y + pos0[nc*3+0];
    const float l1 = b2.z + pos0[nc*3+1];
    const float l2 = b2.w + pos0[nc*3+2];

    // ---- register-resident fp32 frames; sequential half2 pairing at store ----
    float f[8][12];

    #define STORE_FRAME(R) do {                                                   \
        __half2 h0 = __floats2half2_rn(f[R][0],  f[R][1]);                        \
        __half2 h1 = __floats2half2_rn(f[R][2],  f[R][3]);                        \
        __half2 h2 = __floats2half2_rn(f[R][4],  f[R][5]);                        \
        __half2 h3 = __floats2half2_rn(f[R][6],  f[R][7]);                        \
        __half2 h4 = __floats2half2_rn(f[R][8],  f[R][9]);                        \
        __half2 h5 = __floats2half2_rn(f[R][10], f[R][11]);                       \
        uint2 u0; u0.x = *(unsigned*)&h0; u0.y = *(unsigned*)&h1;                 \
        uint2 u1; u1.x = *(unsigned*)&h2; u1.y = *(unsigned*)&h3;                 \
        uint2 u2; u2.x = *(unsigned*)&h4; u2.y = *(unsigned*)&h5;                 \
        s_opr2[((R)*3 + 0)*W + tid] = u0;                                         \
        s_opr2[((R)*3 + 1)*W + tid] = u1;                                         \
        s_opr2[((R)*3 + 2)*W + tid] = u2;                                         \
    } while (0)

    // frame 0: combine(T[rt][0], opr0)
    {
        float X[12];
        #pragma unroll
        for (int cp = 0; cp < 6; cp++) {
            float2 x2 = s_trans2[cp * 21 + rt];
            X[2*cp] = x2.x; X[2*cp+1] = x2.y;
        }
        f[0][0] = X[0]*Y00 + X[1]*Y10 + X[2]*Y20;
        f[0][1] = X[0]*Y01 + X[1]*Y11 + X[2]*Y21;
        f[0][2] = X[0]*Y02 + X[1]*Y12 + X[2]*Y22;
        f[0][3] = X[3]*Y00 + X[4]*Y10 + X[5]*Y20;
        f[0][4] = X[3]*Y01 + X[4]*Y11 + X[5]*Y21;
        f[0][5] = X[3]*Y02 + X[4]*Y12 + X[5]*Y22;
        f[0][6] = X[6]*Y00 + X[7]*Y10 + X[8]*Y20;
        f[0][7] = X[6]*Y01 + X[7]*Y11 + X[8]*Y21;
        f[0][8] = X[6]*Y02 + X[7]*Y12 + X[8]*Y22;
        f[0][9]  = X[0]*l0 + X[1]*l1 + X[2]*l2 + X[9];
        f[0][10] = X[3]*l0 + X[4]*l1 + X[5]*l2 + X[10];
        f[0][11] = X[6]*l0 + X[7]*l1 + X[8]*l2 + X[11];
        STORE_FRAME(0);
    }

    // frames 1..7: SEL-selected prev (exact fp32), single fp16 rounding at store
    #pragma unroll
    for (int r = 1; r < 8; r++) {
        const float cc = cs[r-1].x, ss = cs[r-1].y;

        float Xr[12];
        #pragma unroll
        for (int cp = 0; cp < 6; cp++) {
            float2 x2 = s_trans2[(r*6 + cp) * 21 + rt];
            Xr[2*cp] = x2.x; Xr[2*cp+1] = x2.y;
        }

        // A = T[rt][r] composed with rot_x(c,s)   (translation unchanged)
        const float A0 = Xr[0], A1 = Xr[1]*cc + Xr[2]*ss, A2 = Xr[2]*cc - Xr[1]*ss;
        const float A3 = Xr[3], A4 = Xr[4]*cc + Xr[5]*ss, A5 = Xr[5]*cc - Xr[4]*ss;
        const float A6 = Xr[6], A7 = Xr[7]*cc + Xr[8]*ss, A8 = Xr[8]*cc - Xr[7]*ss;
        const float At0 = Xr[9], At1 = Xr[10], At2 = Xr[11];

        const int dep = (int)(((r < 4 ? dlo : dhi) >> ((r & 3) * 8)) & 0xFFu);

        float P[12];
        #pragma unroll
        for (int k = 0; k < 12; k++) P[k] = f[0][k];
        #pragma unroll
        for (int j = 1; j < 8; j++) {
            if (j < r) {                 // compile-time prune: dep < r
                const bool m = (dep == j);
                #pragma unroll
                for (int k = 0; k < 12; k++) P[k] = m ? f[j][k] : P[k];
            }
        }

        f[r][0] = P[0]*A0 + P[1]*A3 + P[2]*A6;
        f[r][1] = P[0]*A1 + P[1]*A4 + P[2]*A7;
        f[r][2] = P[0]*A2 + P[1]*A5 + P[2]*A8;
        f[r][3] = P[3]*A0 + P[4]*A3 + P[5]*A6;
        f[r][4] = P[3]*A1 + P[4]*A4 + P[5]*A7;
        f[r][5] = P[3]*A2 + P[4]*A5 + P[5]*A8;
        f[r][6] = P[6]*A0 + P[7]*A3 + P[8]*A6;
        f[r][7] = P[6]*A1 + P[7]*A4 + P[8]*A7;
        f[r][8] = P[6]*A2 + P[7]*A5 + P[8]*A8;
        f[r][9]  = P[0]*At0 + P[1]*At1 + P[2]*At2 + P[9];
        f[r][10] = P[3]*At0 + P[4]*At1 + P[5]*At2 + P[10];
        f[r][11] = P[6]*At0 + P[7]*At1 + P[8]*At2 + P[11];

        STORE_FRAME(r);
    }

    __syncwarp();   // atom phase reads frames of the whole warp (this warp produced them)

    // helper: transform one atom through a half2-packed frame
    #define ATOM_XFORM(U0, U1, U2, V0, V1, V2, O0, O1, O2) do {                   \
        float2 M01   = __half22float2(*(const __half2*)&(U0).x);                  \
        float2 M23   = __half22float2(*(const __half2*)&(U0).y);                  \
        float2 M45   = __half22float2(*(const __half2*)&(U1).x);                  \
        float2 M67   = __half22float2(*(const __half2*)&(U1).y);                  \
        float2 M89   = __half22float2(*(const __half2*)&(U2).x);                  \
        float2 M1011 = __half22float2(*(const __half2*)&(U2).y);                  \
        O0 = M01.x*(V0) + M01.y*(V1) + M23.x*(V2) + M89.y;                        \
        O1 = M23.y*(V0) + M45.x*(V1) + M45.y*(V2) + M1011.x;                      \
        O2 = M67.x*(V0) + M67.y*(V1) + M89.x*(V2) + M1011.y;                      \
    } while (0)

    // ---- warp-cooperative quad-task atom phase ----
    // task q = it*32+lane over (res = q/6, quad = q%6); atoms 4*quad..4*quad+3.
    // Output addr = warpbase*72 + 12q floats (48B, 16B-aligned) -> 3 STG.128.
    {
        const int wbase = warp * 32;
        const long resBase = (long)blockIdx.x * BT + wbase;
        float* owarp = out + resBase * 72;

        int res  = lane / 6;        // 0..5
        int quad = lane - res * 6;  // 0..5

        #pragma unroll
        for (int it = 0; it < 6; ++it) {
            const int tres = wbase + res;
            const int rtl  = s_rt[tres];
            const unsigned rq = s_rdquad[quad * 21 + rtl];
            const int rd0 = rq & 0xFF, rd1 = (rq >> 8) & 0xFF;
            const int rd2 = (rq >> 16) & 0xFF, rd3 = rq >> 24;

            uint2 fa0 = s_opr2[(rd0*3 + 0)*W + tres];
            uint2 fa1 = s_opr2[(rd0*3 + 1)*W + tres];
            uint2 fa2 = s_opr2[(rd0*3 + 2)*W + tres];
            uint2 fb0 = s_opr2[(rd1*3 + 0)*W + tres];
            uint2 fb1 = s_opr2[(rd1*3 + 1)*W + tres];
            uint2 fb2 = s_opr2[(rd1*3 + 2)*W + tres];
            uint2 fc0 = s_opr2[(rd2*3 + 0)*W + tres];
            uint2 fc1 = s_opr2[(rd2*3 + 1)*W + tres];
            uint2 fc2 = s_opr2[(rd2*3 + 2)*W + tres];
            uint2 fd0 = s_opr2[(rd3*3 + 0)*W + tres];
            uint2 fd1 = s_opr2[(rd3*3 + 1)*W + tres];
            uint2 fd2 = s_opr2[(rd3*3 + 2)*W + tres];

            uint2 g0 = s_rigq[(quad*3 + 0) * 21 + rtl];
            uint2 g1 = s_rigq[(quad*3 + 1) * 21 + rtl];
            uint2 g2 = s_rigq[(quad*3 + 2) * 21 + rtl];
            const float2 hA = __half22float2(*(const __half2*)&g0.x);  // (v0a,v1a)
            const float2 hB = __half22float2(*(const __half2*)&g0.y);  // (v2a,v0b)
            const float2 hC = __half22float2(*(const __half2*)&g1.x);  // (v1b,v2b)
            const float2 hD = __half22float2(*(const __half2*)&g1.y);  // (v0c,v1c)
            const float2 hE = __half22float2(*(const __half2*)&g2.x);  // (v2c,v0d)
            const float2 hF = __half22float2(*(const __half2*)&g2.y);  // (v1d,v2d)

            float o[12];
            ATOM_XFORM(fa0, fa1, fa2, hA.x, hA.y, hB.x, o[0],  o[1],  o[2]);
            ATOM_XFORM(fb0, fb1, fb2, hB.y, hC.x, hC.y, o[3],  o[4],  o[5]);
            ATOM_XFORM(fc0, fc1, fc2, hD.x, hD.y, hE.x, o[6],  o[7],  o[8]);
            ATOM_XFORM(fd0, fd1, fd2, hE.y, hF.x, hF.y, o[9],  o[10], o[11]);

            if (resBase + res < (long)nres) {
                float4* pp = (float4*)(owarp + res * 72 + quad * 12);
                pp[0] = make_float4(o[0], o[1], o[2],  o[3]);
                pp[1] = make_float4(o[4], o[5], o[6],  o[7]);
                pp[2] = make_float4(o[8], o[9], o[10], o[11]);
            }
            // advance task by 32: res += 5, quad += 2, carry on quad wrap
            res += 5; quad += 2;
            if (quad >= 6) { quad -= 6; res += 1; }
        }
    }

    // ---- second output: opr[:,0] (frame 0, sequential halves), coalesced ----
    {
        const int wbase = warp * 32;
        const long resBase = (long)blockIdx.x * BT + wbase;
        long rem = (long)nres - resBase;
        const int cnt = (rem >= 32) ? 32 : (rem > 0 ? (int)rem : 0);
        float* o2 = out + (long)nres * 72 + resBase * 12;
        const int tot = cnt * 12;
        for (int k = lane; k < tot; k += 32) {
            const int l = k / 12;
            const int c = k - l * 12;          // component 0..11 -> (q = c/4, half = c%4)
            const char* basep = (const char*)&s_opr2[(c >> 2)*W + wbase + l];
            const __half h = *(const __half*)(basep + (c & 3) * 2);
            o2[k] = __half2float(h);
        }
    }
}

extern "C" void kernel_launch(void* const* d_in, const int* in_sizes, int n_in,
                              void* d_out, int out_size)
{
    const int*   rtype   = (const int*)  d_in[0];
    const float* bb      = (const float*)d_in[1];
    const float* pos0    = (const float*)d_in[2];
    const float* sc      = (const float*)d_in[3];
    const float* g_trans = (const float*)d_in[4];
    const float* g_rig   = (const float*)d_in[5];
    const int*   g_tdep  = (const int*)  d_in[6];
    const int*   g_rdep  = (const int*)  d_in[7];
    float* out = (float*)d_out;

    const int nres = in_sizes[0];

    cudaFuncSetAttribute(backbone_kernel,
                         cudaFuncAttributeMaxDynamicSharedMemorySize, SMEM_BYTES);

    const int grid = (nres + BT - 1) / BT;
    backbone_kernel<<<grid, BT, SMEM_BYTES>>>(rtype, bb, pos0, sc,
                                              g_trans, g_rig, g_tdep, g_rdep,
                                              out, nres);
}

// round 17
// speedup vs baseline: 1.5465x; 1.0898x over previous
#include <cuda_runtime.h>
#include <cuda_fp16.h>

// N=524288 residues, 21 residue types, 8 rigid frames, 24 atoms (6 atom-quads).
// Chain state packed fp16x2 in registers (48 regs) -> 3 blocks x 224 = 21 warps/SM.
static constexpr int BT = 224;   // threads per block, 1 thread = 1 residue in build phase
static constexpr int W  = 225;   // uint2-row stride for frames (225 == 1 mod 32 -> conflict-free)

// Shared memory layout (word offsets)
static constexpr int S_TRANS2 = 0;                    // 48*21 float2 = 2016 words
static constexpr int S_RIGQ   = S_TRANS2 + 48*21*2;   // 6*3*21 uint2 = 756 words
static constexpr int S_RT     = S_RIGQ   + 6*3*21*2;  // BT ints
static constexpr int S_TDEPP  = S_RT     + BT;        // 2*21 u32 packed tdep bytes
static constexpr int S_RDQUAD = S_TDEPP  + 2*21;      // 6*21 u32 = 126 words
static constexpr int S_OPR2   = S_RDQUAD + 126;       // 24 rows * W uint2
static constexpr int SMEM_WORDS = S_OPR2 + 24 * W * 2;
static constexpr int SMEM_BYTES = SMEM_WORDS * 4;     // 55,856 B -> 3 blocks/SM

static_assert(S_OPR2 % 2 == 0, "uint2 region must be 8B aligned");
static_assert(S_RIGQ % 2 == 0, "rigq region must be 8B aligned");

__global__ void __launch_bounds__(BT, 3)
backbone_kernel(const int* __restrict__ rtype,
                const float* __restrict__ bb,       // (N,4,3)
                const float* __restrict__ pos0,     // (N,3)
                const float* __restrict__ sc,       // (N,7,2)
                const float* __restrict__ g_trans,  // (21,8,4,3)
                const float* __restrict__ g_rig,    // (21,24,3)
                const int* __restrict__ g_tdep,     // (21,8)
                const int* __restrict__ g_rdep,     // (21,24)
                float* __restrict__ out, int nres)
{
    extern __shared__ float sm[];
    float2*         s_trans2 = (float2*)(sm + S_TRANS2);
    uint2*          s_rigq   = (uint2*)(sm + S_RIGQ);
    int*            s_rt     = (int*)(sm + S_RT);
    unsigned*       s_tdepp  = (unsigned*)(sm + S_TDEPP);
    unsigned*       s_rdquad = (unsigned*)(sm + S_RDQUAD);
    uint2*          s_opr2   = (uint2*)(sm + S_OPR2);  // index: (frame*3 + q)*W + tid

    const int tid  = threadIdx.x;
    const int lane = tid & 31;
    const int warp = tid >> 5;

    // ---- stage tables (stride-21 transposed -> conflict-free divergent-rt reads) ----
    {
        float* t2f = (float*)s_trans2;
        for (int i = tid; i < 96 * 21; i += BT) {
            const int rtt = i / 96, comp = i % 96;
            t2f[((comp >> 1) * 21 + rtt) * 2 + (comp & 1)] = g_trans[i];
        }
        // rig packed per atom-quad as 6 half2 (12 values: atoms 4q..4q+3)
        for (int i = tid; i < 6 * 21; i += BT) {
            const int q = i % 6, rtt = i / 6;
            const float* gr = g_rig + rtt * 72 + q * 12;
            #pragma unroll
            for (int k = 0; k < 3; k++) {
                __half2 hx = __floats2half2_rn(gr[4*k + 0], gr[4*k + 1]);
                __half2 hy = __floats2half2_rn(gr[4*k + 2], gr[4*k + 3]);
                uint2 u; u.x = *(unsigned*)&hx; u.y = *(unsigned*)&hy;
                s_rigq[(q * 3 + k) * 21 + rtt] = u;
            }
        }
        // rdep packed 4 bytes per quad
        for (int i = tid; i < 6 * 21; i += BT) {
            const int q = i % 6, rtt = i / 6;
            unsigned wv = 0;
            #pragma unroll
            for (int b = 0; b < 4; b++)
                wv |= ((unsigned)g_rdep[rtt * 24 + q * 4 + b] & 0xFFu) << (8 * b);
            s_rdquad[q * 21 + rtt] = wv;
        }
        for (int i = tid; i < 2 * 21; i += BT) {
            const int rtt = i >> 1, h = i & 1;
            unsigned wv = 0;
            #pragma unroll
            for (int b = 0; b < 4; b++)
                wv |= ((unsigned)g_tdep[rtt * 8 + h * 4 + b] & 0xFFu) << (8 * b);
            s_tdepp[i] = wv;
        }
    }
    __syncthreads();

    const long resG = (long)blockIdx.x * BT + tid;
    const int nc = (resG < (long)nres) ? (int)resG : (nres - 1);
    const int rt = rtype[nc];
    s_rt[tid] = rt;

    const unsigned dlo = s_tdepp[rt * 2 + 0];
    const unsigned dhi = s_tdepp[rt * 2 + 1];

    // ---- per-residue inputs: ALL prefetched to registers before the chain ----
    const float4* bb4 = (const float4*)bb + (size_t)nc * 3;
    float4 b0 = bb4[0], b1 = bb4[1], b2 = bb4[2];
    const float2* sc2 = (const float2*)sc + (size_t)nc * 7;
    float2 cs[7];
    #pragma unroll
    for (int r = 0; r < 7; r++) cs[r] = sc2[r];

    const float Y00=b0.x, Y01=b0.y, Y02=b0.z;
    const float Y10=b0.w, Y11=b1.x, Y12=b1.y;
    const float Y20=b1.z, Y21=b1.w, Y22=b2.x;
    const float l0 = b2.y + pos0[nc*3+0];
    const float l1 = b2.z + pos0[nc*3+1];
    const float l2 = b2.w + pos0[nc*3+2];

    // ---- packed fp16x2 register frames: fpk[r][0..5] = (m0m1|m2m3|...|m10m11) ----
    unsigned fpk[8][6];

    #define PACK_FRAME(R, C) do {                                                 \
        __half2 _h0 = __floats2half2_rn((C)[0],  (C)[1]);                         \
        __half2 _h1 = __floats2half2_rn((C)[2],  (C)[3]);                         \
        __half2 _h2 = __floats2half2_rn((C)[4],  (C)[5]);                         \
        __half2 _h3 = __floats2half2_rn((C)[6],  (C)[7]);                         \
        __half2 _h4 = __floats2half2_rn((C)[8],  (C)[9]);                         \
        __half2 _h5 = __floats2half2_rn((C)[10], (C)[11]);                        \
        fpk[R][0] = *(unsigned*)&_h0;  fpk[R][1] = *(unsigned*)&_h1;              \
        fpk[R][2] = *(unsigned*)&_h2;  fpk[R][3] = *(unsigned*)&_h3;              \
        fpk[R][4] = *(unsigned*)&_h4;  fpk[R][5] = *(unsigned*)&_h5;              \
    } while (0)

    #define STORE_FRAME(R) do {                                                   \
        uint2 u0; u0.x = fpk[R][0]; u0.y = fpk[R][1];                             \
        uint2 u1; u1.x = fpk[R][2]; u1.y = fpk[R][3];                             \
        uint2 u2; u2.x = fpk[R][4]; u2.y = fpk[R][5];                             \
        s_opr2[((R)*3 + 0)*W + tid] = u0;                                         \
        s_opr2[((R)*3 + 1)*W + tid] = u1;                                         \
        s_opr2[((R)*3 + 2)*W + tid] = u2;                                         \
    } while (0)

    // frame 0: combine(T[rt][0], opr0) in fp32, single rounding at pack
    {
        float X[12];
        #pragma unroll
        for (int cp = 0; cp < 6; cp++) {
            float2 x2 = s_trans2[cp * 21 + rt];
            X[2*cp] = x2.x; X[2*cp+1] = x2.y;
        }
        float C[12];
        C[0] = X[0]*Y00 + X[1]*Y10 + X[2]*Y20;
        C[1] = X[0]*Y01 + X[1]*Y11 + X[2]*Y21;
        C[2] = X[0]*Y02 + X[1]*Y12 + X[2]*Y22;
        C[3] = X[3]*Y00 + X[4]*Y10 + X[5]*Y20;
        C[4] = X[3]*Y01 + X[4]*Y11 + X[5]*Y21;
        C[5] = X[3]*Y02 + X[4]*Y12 + X[5]*Y22;
        C[6] = X[6]*Y00 + X[7]*Y10 + X[8]*Y20;
        C[7] = X[6]*Y01 + X[7]*Y11 + X[8]*Y21;
        C[8] = X[6]*Y02 + X[7]*Y12 + X[8]*Y22;
        C[9]  = X[0]*l0 + X[1]*l1 + X[2]*l2 + X[9];
        C[10] = X[3]*l0 + X[4]*l1 + X[5]*l2 + X[10];
        C[11] = X[6]*l0 + X[7]*l1 + X[8]*l2 + X[11];
        PACK_FRAME(0, C);
        STORE_FRAME(0);
    }

    // frames 1..7: packed SEL tree (6 SELs/candidate), unpack selected prev, fp32 math
    #pragma unroll
    for (int r = 1; r < 8; r++) {
        const float cc = cs[r-1].x, ss = cs[r-1].y;

        float Xr[12];
        #pragma unroll
        for (int cp = 0; cp < 6; cp++) {
            float2 x2 = s_trans2[(r*6 + cp) * 21 + rt];
            Xr[2*cp] = x2.x; Xr[2*cp+1] = x2.y;
        }

        // A = T[rt][r] composed with rot_x(c,s)   (translation unchanged)
        const float A0 = Xr[0], A1 = Xr[1]*cc + Xr[2]*ss, A2 = Xr[2]*cc - Xr[1]*ss;
        const float A3 = Xr[3], A4 = Xr[4]*cc + Xr[5]*ss, A5 = Xr[5]*cc - Xr[4]*ss;
        const float A6 = Xr[6], A7 = Xr[7]*cc + Xr[8]*ss, A8 = Xr[8]*cc - Xr[7]*ss;
        const float At0 = Xr[9], At1 = Xr[10], At2 = Xr[11];

        const int dep = (int)(((r < 4 ? dlo : dhi) >> ((r & 3) * 8)) & 0xFFu);

        unsigned s0 = fpk[0][0], s1 = fpk[0][1], s2 = fpk[0][2];
        unsigned s3 = fpk[0][3], s4 = fpk[0][4], s5 = fpk[0][5];
        #pragma unroll
        for (int j = 1; j < 8; j++) {
            if (j < r) {                 // compile-time prune: dep < r
                const bool m = (dep == j);
                s0 = m ? fpk[j][0] : s0;  s1 = m ? fpk[j][1] : s1;
                s2 = m ? fpk[j][2] : s2;  s3 = m ? fpk[j][3] : s3;
                s4 = m ? fpk[j][4] : s4;  s5 = m ? fpk[j][5] : s5;
            }
        }

        const float2 p01   = __half22float2(*(const __half2*)&s0);
        const float2 p23   = __half22float2(*(const __half2*)&s1);
        const float2 p45   = __half22float2(*(const __half2*)&s2);
        const float2 p67   = __half22float2(*(const __half2*)&s3);
        const float2 p89   = __half22float2(*(const __half2*)&s4);
        const float2 p1011 = __half22float2(*(const __half2*)&s5);
        const float P0=p01.x, P1=p01.y, P2=p23.x, P3=p23.y, P4=p45.x, P5=p45.y;
        const float P6=p67.x, P7=p67.y, P8=p89.x, P9=p89.y, P10=p1011.x, P11=p1011.y;

        float C[12];
        C[0] = P0*A0 + P1*A3 + P2*A6;
        C[1] = P0*A1 + P1*A4 + P2*A7;
        C[2] = P0*A2 + P1*A5 + P2*A8;
        C[3] = P3*A0 + P4*A3 + P5*A6;
        C[4] = P3*A1 + P4*A4 + P5*A7;
        C[5] = P3*A2 + P4*A5 + P5*A8;
        C[6] = P6*A0 + P7*A3 + P8*A6;
        C[7] = P6*A1 + P7*A4 + P8*A7;
        C[8] = P6*A2 + P7*A5 + P8*A8;
        C[9]  = P0*At0 + P1*At1 + P2*At2 + P9;
        C[10] = P3*At0 + P4*At1 + P5*At2 + P10;
        C[11] = P6*At0 + P7*At1 + P8*At2 + P11;

        PACK_FRAME(r, C);
        STORE_FRAME(r);
    }

    __syncwarp();   // atom phase reads frames of the whole warp (this warp produced them)

    // helper: transform one atom through a half2-packed frame
    #define ATOM_XFORM(U0, U1, U2, V0, V1, V2, O0, O1, O2) do {                   \
        float2 M01   = __half22float2(*(const __half2*)&(U0).x);                  \
        float2 M23   = __half22float2(*(const __half2*)&(U0).y);                  \
        float2 M45   = __half22float2(*(const __half2*)&(U1).x);                  \
        float2 M67   = __half22float2(*(const __half2*)&(U1).y);                  \
        float2 M89   = __half22float2(*(const __half2*)&(U2).x);                  \
        float2 M1011 = __half22float2(*(const __half2*)&(U2).y);                  \
        O0 = M01.x*(V0) + M01.y*(V1) + M23.x*(V2) + M89.y;                        \
        O1 = M23.y*(V0) + M45.x*(V1) + M45.y*(V2) + M1011.x;                      \
        O2 = M67.x*(V0) + M67.y*(V1) + M89.x*(V2) + M1011.y;                      \
    } while (0)

    // ---- warp-cooperative quad-task atom phase ----
    // task q = it*32+lane over (res = q/6, quad = q%6); atoms 4*quad..4*quad+3.
    // Output addr = warpbase*72 + 12q floats (48B, 16B-aligned) -> 3 STG.128.
    {
        const int wbase = warp * 32;
        const long resBase = (long)blockIdx.x * BT + wbase;
        float* owarp = out + resBase * 72;

        int res  = lane / 6;        // 0..5
        int quad = lane - res * 6;  // 0..5

        #pragma unroll
        for (int it = 0; it < 6; ++it) {
            const int tres = wbase + res;
            const int rtl  = s_rt[tres];
            const unsigned rq = s_rdquad[quad * 21 + rtl];
            const int rd0 = rq & 0xFF, rd1 = (rq >> 8) & 0xFF;
            const int rd2 = (rq >> 16) & 0xFF, rd3 = rq >> 24;

            uint2 fa0 = s_opr2[(rd0*3 + 0)*W + tres];
            uint2 fa1 = s_opr2[(rd0*3 + 1)*W + tres];
            uint2 fa2 = s_opr2[(rd0*3 + 2)*W + tres];
            uint2 fb0 = s_opr2[(rd1*3 + 0)*W + tres];
            uint2 fb1 = s_opr2[(rd1*3 + 1)*W + tres];
            uint2 fb2 = s_opr2[(rd1*3 + 2)*W + tres];
            uint2 fc0 = s_opr2[(rd2*3 + 0)*W + tres];
            uint2 fc1 = s_opr2[(rd2*3 + 1)*W + tres];
            uint2 fc2 = s_opr2[(rd2*3 + 2)*W + tres];
            uint2 fd0 = s_opr2[(rd3*3 + 0)*W + tres];
            uint2 fd1 = s_opr2[(rd3*3 + 1)*W + tres];
            uint2 fd2 = s_opr2[(rd3*3 + 2)*W + tres];

            uint2 g0 = s_rigq[(quad*3 + 0) * 21 + rtl];
            uint2 g1 = s_rigq[(quad*3 + 1) * 21 + rtl];
            uint2 g2 = s_rigq[(quad*3 + 2) * 21 + rtl];
            const float2 hA = __half22float2(*(const __half2*)&g0.x);  // (v0a,v1a)
            const float2 hB = __half22float2(*(const __half2*)&g0.y);  // (v2a,v0b)
            const float2 hC = __half22float2(*(const __half2*)&g1.x);  // (v1b,v2b)
            const float2 hD = __half22float2(*(const __half2*)&g1.y);  // (v0c,v1c)
            const float2 hE = __half22float2(*(const __half2*)&g2.x);  // (v2c,v0d)
            const float2 hF = __half22float2(*(const __half2*)&g2.y);  // (v1d,v2d)

            float o[12];
            ATOM_XFORM(fa0, fa1, fa2, hA.x, hA.y, hB.x, o[0],  o[1],  o[2]);
            ATOM_XFORM(fb0, fb1, fb2, hB.y, hC.x, hC.y, o[3],  o[4],  o[5]);
            ATOM_XFORM(fc0, fc1, fc2, hD.x, hD.y, hE.x, o[6],  o[7],  o[8]);
            ATOM_XFORM(fd0, fd1, fd2, hE.y, hF.x, hF.y, o[9],  o[10], o[11]);

            if (resBase + res < (long)nres) {
                float4* pp = (float4*)(owarp + res * 72 + quad * 12);
                pp[0] = make_float4(o[0], o[1], o[2],  o[3]);
                pp[1] = make_float4(o[4], o[5], o[6],  o[7]);
                pp[2] = make_float4(o[8], o[9], o[10], o[11]);
            }
            // advance task by 32: res += 5, quad += 2, carry on quad wrap
            res += 5; quad += 2;
            if (quad >= 6) { quad -= 6; res += 1; }
        }
    }

    // ---- second output: opr[:,0] (frame 0, sequential halves), coalesced ----
    {
        const int wbase = warp * 32;
        const long resBase = (long)blockIdx.x * BT + wbase;
        long rem = (long)nres - resBase;
        const int cnt = (rem >= 32) ? 32 : (rem > 0 ? (int)rem : 0);
        float* o2 = out + (long)nres * 72 + resBase * 12;
        const int tot = cnt * 12;
        for (int k = lane; k < tot; k += 32) {
            const int l = k / 12;
            const int c = k - l * 12;          // component 0..11 -> (q = c/4, half = c%4)
            const char* basep = (const char*)&s_opr2[(c >> 2)*W + wbase + l];
            const __half h = *(const __half*)(basep + (c & 3) * 2);
            o2[k] = __half2float(h);
        }
    }
}

extern "C" void kernel_launch(void* const* d_in, const int* in_sizes, int n_in,
                              void* d_out, int out_size)
{
    const int*   rtype   = (const int*)  d_in[0];
    const float* bb      = (const float*)d_in[1];
    const float* pos0    = (const float*)d_in[2];
    const float* sc      = (const float*)d_in[3];
    const float* g_trans = (const float*)d_in[4];
    const float* g_rig   = (const float*)d_in[5];
    const int*   g_tdep  = (const int*)  d_in[6];
    const int*   g_rdep  = (const int*)  d_in[7];
    float* out = (float*)d_out;

    const int nres = in_sizes[0];

    cudaFuncSetAttribute(backbone_kernel,
                         cudaFuncAttributeMaxDynamicSharedMemorySize, SMEM_BYTES);

    const int grid = (nres + BT - 1) / BT;
    backbone_kernel<<<grid, BT, SMEM_BYTES>>>(rtype, bb, pos0, sc,
                                              g_trans, g_rig, g_tdep, g_rdep,
                                              out, nres);
}